// round 17
// baseline (speedup 1.0000x reference)
#include <cuda_runtime.h>
#include <cuda_bf16.h>
#include <cstdint>

#define BATCH 64
#define SEQ   1024
#define IDIM  256
#define HDIM  512
#define ODIM  128
#define G4    2048

typedef unsigned long long ull;

// ---------------- device scratch ----------------
__device__ float g_xp[(size_t)SEQ * BATCH * G4];          // input projection [t*64+b][4H]
__device__ __nv_bfloat16 g_hh[2][BATCH * HDIM];           // h (bf16), double-buffered
__device__ float g_last[BATCH * 2 * HDIM];
__device__ ull g_flags[1024][16];                         // per (block,warp) padded flags

__device__ __forceinline__ float sigf(float v) {
    return __fdividef(1.0f, 1.0f + __expf(-v));
}
__device__ __forceinline__ float tanhf_fast(float v) {
    float e = __expf(2.0f * v);
    return __fdividef(e - 1.0f, e + 1.0f);
}
__device__ __forceinline__ uint32_t packbf2(__nv_bfloat16 lo_elem, __nv_bfloat16 hi_elem) {
    return (uint32_t)__bfloat16_as_ushort(lo_elem) |
           ((uint32_t)__bfloat16_as_ushort(hi_elem) << 16);
}
__device__ __forceinline__ void mma16816(
    float& d0, float& d1, float& d2, float& d3,
    uint32_t a0, uint32_t a1, uint32_t a2, uint32_t a3,
    uint32_t b0, uint32_t b1)
{
    asm volatile(
        "mma.sync.aligned.m16n8k16.row.col.f32.bf16.bf16.f32 "
        "{%0,%1,%2,%3},{%4,%5,%6,%7},{%8,%9},{%0,%1,%2,%3};"
        : "+f"(d0), "+f"(d1), "+f"(d2), "+f"(d3)
        : "r"(a0), "r"(a1), "r"(a2), "r"(a3), "r"(b0), "r"(b1));
}

// ================================================================
// Kernel 1: xp = relu(x) @ W_ih_f^T + b_f  — TC, 128x128x64 (R16).
// ================================================================
#define XBM 128
#define XBN 128
#define XBK 64
#define XST 36
#define XGEMM_SMEM ((2*XBM*XST + 2*XBN*XST) * 4)

__global__ void __launch_bounds__(256, 2) gemm_xp_kernel(
    const float* __restrict__ x,
    const float* __restrict__ Wih, const float* __restrict__ bias)
{
    extern __shared__ uint32_t smx[];
    uint32_t* Ah = smx;
    uint32_t* Al = Ah + XBM * XST;
    uint32_t* Bh = Al + XBM * XST;
    uint32_t* Bl = Bh + XBN * XST;

    const int tid  = threadIdx.x;
    const int lane = tid & 31, wid = tid >> 5;
    const int n0 = blockIdx.x * XBN;
    const int t0 = blockIdx.y * 2;

    const int mw = wid >> 1;
    const int nw = wid & 1;
    const int g = lane >> 2, tig = lane & 3;

    float C[2][8][4];
#pragma unroll
    for (int mt = 0; mt < 2; mt++)
#pragma unroll
        for (int nt = 0; nt < 8; nt++)
            C[mt][nt][0] = C[mt][nt][1] = C[mt][nt][2] = C[mt][nt][3] = 0.f;

#pragma unroll 1
    for (int ko = 0; ko < IDIM; ko += XBK) {
#pragma unroll
        for (int i = 0; i < 8; i++) {
            int u = tid + i * 256;
            int row = u >> 4, q = u & 15;
            int b = row & 63, tt = t0 + (row >> 6);
            float4 v = __ldcg((const float4*)(x + ((size_t)b * SEQ + tt) * IDIM + ko + q * 4));
            v.x = fmaxf(v.x, 0.f); v.y = fmaxf(v.y, 0.f);
            v.z = fmaxf(v.z, 0.f); v.w = fmaxf(v.w, 0.f);
            __nv_bfloat16 h0 = __float2bfloat16(v.x), h1 = __float2bfloat16(v.y);
            __nv_bfloat16 h2 = __float2bfloat16(v.z), h3 = __float2bfloat16(v.w);
            __nv_bfloat16 l0 = __float2bfloat16(v.x - __bfloat162float(h0));
            __nv_bfloat16 l1 = __float2bfloat16(v.y - __bfloat162float(h1));
            __nv_bfloat16 l2 = __float2bfloat16(v.z - __bfloat162float(h2));
            __nv_bfloat16 l3 = __float2bfloat16(v.w - __bfloat162float(h3));
            *(uint2*)(Ah + row * XST + q * 2) = make_uint2(packbf2(h0, h1), packbf2(h2, h3));
            *(uint2*)(Al + row * XST + q * 2) = make_uint2(packbf2(l0, l1), packbf2(l2, l3));
        }
#pragma unroll
        for (int i = 0; i < 8; i++) {
            int u = tid + i * 256;
            int row = u >> 4, q = u & 15;
            float4 v = __ldcg((const float4*)(Wih + (size_t)(n0 + row) * IDIM + ko + q * 4));
            __nv_bfloat16 h0 = __float2bfloat16(v.x), h1 = __float2bfloat16(v.y);
            __nv_bfloat16 h2 = __float2bfloat16(v.z), h3 = __float2bfloat16(v.w);
            __nv_bfloat16 l0 = __float2bfloat16(v.x - __bfloat162float(h0));
            __nv_bfloat16 l1 = __float2bfloat16(v.y - __bfloat162float(h1));
            __nv_bfloat16 l2 = __float2bfloat16(v.z - __bfloat162float(h2));
            __nv_bfloat16 l3 = __float2bfloat16(v.w - __bfloat162float(h3));
            *(uint2*)(Bh + row * XST + q * 2) = make_uint2(packbf2(h0, h1), packbf2(h2, h3));
            *(uint2*)(Bl + row * XST + q * 2) = make_uint2(packbf2(l0, l1), packbf2(l2, l3));
        }
        __syncthreads();

#pragma unroll
        for (int ks = 0; ks < 4; ks++) {
            int w = ks * 8;
            uint32_t ah[2][4], al[2][4];
#pragma unroll
            for (int mt = 0; mt < 2; mt++) {
                int r0 = (mw * 32 + mt * 16 + g) * XST + w + tig;
                int r1 = r0 + 8 * XST;
                ah[mt][0] = Ah[r0]; ah[mt][1] = Ah[r1];
                ah[mt][2] = Ah[r0 + 4]; ah[mt][3] = Ah[r1 + 4];
                al[mt][0] = Al[r0]; al[mt][1] = Al[r1];
                al[mt][2] = Al[r0 + 4]; al[mt][3] = Al[r1 + 4];
            }
#pragma unroll
            for (int nt = 0; nt < 8; nt++) {
                int c = (nw * 64 + nt * 8 + g) * XST + w + tig;
                uint32_t bh0 = Bh[c], bh1 = Bh[c + 4];
                uint32_t bl0 = Bl[c], bl1 = Bl[c + 4];
#pragma unroll
                for (int mt = 0; mt < 2; mt++) {
                    mma16816(C[mt][nt][0], C[mt][nt][1], C[mt][nt][2], C[mt][nt][3],
                             ah[mt][0], ah[mt][1], ah[mt][2], ah[mt][3], bh0, bh1);
                    mma16816(C[mt][nt][0], C[mt][nt][1], C[mt][nt][2], C[mt][nt][3],
                             al[mt][0], al[mt][1], al[mt][2], al[mt][3], bh0, bh1);
                    mma16816(C[mt][nt][0], C[mt][nt][1], C[mt][nt][2], C[mt][nt][3],
                             ah[mt][0], ah[mt][1], ah[mt][2], ah[mt][3], bl0, bl1);
                }
            }
        }
        __syncthreads();
    }

#pragma unroll
    for (int mt = 0; mt < 2; mt++) {
#pragma unroll
        for (int nt = 0; nt < 8; nt++) {
            int col = n0 + nw * 64 + nt * 8 + tig * 2;
            float2 bv = *(const float2*)(bias + col);
            int ml = mw * 32 + mt * 16 + g;
            int rowg = (t0 + (ml >> 6)) * BATCH + (ml & 63);
            float2 o0 = { C[mt][nt][0] + bv.x, C[mt][nt][1] + bv.y };
            *(float2*)(g_xp + (size_t)rowg * G4 + col) = o0;
            ml += 8;
            rowg = (t0 + (ml >> 6)) * BATCH + (ml & 63);
            float2 o1 = { C[mt][nt][2] + bv.x, C[mt][nt][3] + bv.y };
            *(float2*)(g_xp + (size_t)rowg * G4 + col) = o1;
        }
    }
}

// ================================================================
// Kernel 2: backward-direction last hidden state (unchanged)
// ================================================================
__global__ void __launch_bounds__(256) bwd_last_kernel(
    const float* __restrict__ x,
    const float* __restrict__ Wb, const float* __restrict__ bb)
{
    __shared__ float xs[IDIM];
    const int b = blockIdx.x, tid = threadIdx.x;
    xs[tid] = fmaxf(x[((size_t)b * SEQ + (SEQ - 1)) * IDIM + tid], 0.f);
    __syncthreads();

    const int j = blockIdx.y * 256 + tid;
    const int cols[3] = { j, 2 * HDIM + j, 3 * HDIM + j };
    float acc[3] = { bb[cols[0]], bb[cols[1]], bb[cols[2]] };
#pragma unroll
    for (int gi = 0; gi < 3; gi++) {
        const float4* wp = (const float4*)(Wb + (size_t)cols[gi] * IDIM);
        float s = 0.f;
#pragma unroll 8
        for (int k4 = 0; k4 < IDIM / 4; k4++) {
            float4 w = __ldg(wp + k4);
            float4 xv = *(const float4*)&xs[k4 * 4];
            s += w.x * xv.x + w.y * xv.y + w.z * xv.z + w.w * xv.w;
        }
        acc[gi] += s;
    }
    float cst = sigf(acc[0]) * tanhf_fast(acc[1]);
    float h   = sigf(acc[2]) * tanhf_fast(cst);
    g_last[b * (2 * HDIM) + HDIM + j] = h;
}

// ================================================================
// Kernel 3: persistent LSTM scan — PER-WARP producer flags.
// Producer warp w of block bid owns batches 2w,2w+1 (its update
// lanes). After its h stores: __syncwarp (intra-warp sync-with)
// then lane0 st.release on flag[bid*8+w]. No block-wide sync
// before release. Consumer lane (staging row srow=lane>>1 of
// producers 4*wid..4*wid+3) needs exactly producer-warp srow>>1
// -> waits on its 4 specific (block,warp) flags. Union over the
// block's warps covers all 32 producers x 8 warps; post-staging
// __syncthreads joins -> same WAR guarantees as the full barrier.
// ================================================================
#define SCAN_BLOCKS 128
#define SCAN_THREADS 256
#define WST 260                 // words per 512-elem bf16 row (256 + 4 pad)
#define GSP 68
#define SCAN_SMEM ((2*64*WST + 16*WST + 2*16*GSP) * 4)

__global__ void __launch_bounds__(SCAN_THREADS, 1) lstm_scan_kernel(const float* __restrict__ Whh)
{
    extern __shared__ uint32_t smw[];
    uint32_t* ws_hi = smw;                    // [64][WST]
    uint32_t* ws_lo = smw + 64 * WST;
    uint32_t* hs    = smw + 2 * 64 * WST;     // [16][WST] h (bf16)
    float*    gs2   = (float*)(hs + 16 * WST);  // [2][16][GSP]

    const int tid  = threadIdx.x;
    const int bid  = blockIdx.x;
    const int bg   = bid >> 5;
    const int jg   = bid & 31;
    const int fbase = bg * 32;
    const int lane = tid & 31;
    const int wid  = tid >> 5;

    // ---- one-time W_hh slice load + hi/lo split ----
#pragma unroll 1
    for (int u = tid; u < 64 * 256; u += SCAN_THREADS) {
        int lc = u >> 8;
        int w  = u & 255;
        int grow = (lc >> 4) * HDIM + jg * 16 + (lc & 15);
        float2 v = *(const float2*)(Whh + (size_t)grow * HDIM + w * 2);
        __nv_bfloat16 h0 = __float2bfloat16(v.x);
        __nv_bfloat16 h1 = __float2bfloat16(v.y);
        __nv_bfloat16 l0 = __float2bfloat16(v.x - __bfloat162float(h0));
        __nv_bfloat16 l1 = __float2bfloat16(v.y - __bfloat162float(h1));
        ws_hi[lc * WST + w] = packbf2(h0, h1);
        ws_lo[lc * WST + w] = packbf2(l0, l1);
    }

    const int g   = lane >> 2, tig = lane & 3;
    const int kh  = wid >> 2;
    const int nw  = wid & 3;
    const int nc0 = nw * 16;
    const int hb0 = g * WST + tig;
    const int hb1 = (g + 8) * WST + tig;
    const int wb0 = (nc0 + g) * WST + tig;
    const int wb1 = (nc0 + 8 + g) * WST + tig;
    const int kw0 = kh * 128;
    float* gso = gs2 + kh * 16 * GSP;

    const int ub = tid >> 4, uj = tid & 15;
    const int batch = bg * 16 + ub;
    const int jcol  = jg * 16 + uj;
    float cstate = 0.f;
    __nv_bfloat16* hh0 = &g_hh[0][batch * HDIM + jcol];
    __nv_bfloat16* hh1 = &g_hh[1][batch * HDIM + jcol];
    const size_t tstride = (size_t)BATCH * G4;
    const float* xpi = g_xp + (size_t)batch * G4 + 0 * HDIM + jcol;
    const float* xpf = g_xp + (size_t)batch * G4 + 1 * HDIM + jcol;
    const float* xpg = g_xp + (size_t)batch * G4 + 2 * HDIM + jcol;
    const float* xpo = g_xp + (size_t)batch * G4 + 3 * HDIM + jcol;
    float xvi = __ldcs(xpi), xvf = __ldcs(xpf);
    float xvg = __ldcs(xpg), xvo = __ldcs(xpo);

    // staging role: warp owns producers 4*wid..4*wid+3; lane -> (row, half)
    const int srow = lane >> 1, shalf = lane & 1;
    const int pwarp = lane >> 2;              // producer warp needed for row group

    // release flag for this (block, warp)
    ull* myflag = &g_flags[bid * 8 + wid][0];

#define WARP_RELEASE(VAL) do{                                                  \
    __syncwarp();                                                              \
    if (lane == 0)                                                             \
        asm volatile("st.release.gpu.global.u64 [%0], %1;"                     \
                     :: "l"(myflag), "l"((ull)(VAL)) : "memory");              \
}while(0)

    // ---- t = 0: h = 0 -> gates = xp ----
    {
        float i_ = sigf(xvi), f_ = sigf(xvf);
        float gv = tanhf_fast(xvg), o_ = sigf(xvo);
        cstate = fmaf(f_, cstate, i_ * gv);
        float h = o_ * tanhf_fast(cstate);
        *hh1 = __float2bfloat16(h);
        xvi = __ldcs(xpi + tstride); xvf = __ldcs(xpf + tstride);
        xvg = __ldcs(xpg + tstride); xvo = __ldcs(xpo + tstride);
    }
    WARP_RELEASE(1);

#pragma unroll 1
    for (int t = 1; t < SEQ; t++) {
        // ---- per-lane wait: 4 producers' warp pwarp flags >= t ----
        {
#pragma unroll
            for (int pp = 0; pp < 4; pp++) {
                int p = (wid << 2) + pp;
                const ull* fp = &g_flags[(fbase + p) * 8 + pwarp][0];
                ull v;
                do {
                    asm volatile("ld.acquire.gpu.global.u64 %0, [%1];"
                                 : "=l"(v) : "l"(fp) : "memory");
                } while (v < (ull)t);
            }
            __syncwarp();
        }
        // ---- stage this warp's 4 producer chunks (16 rows x 32B each) ----
        {
            const __nv_bfloat16* hbase = g_hh[t & 1] + (size_t)bg * 16 * HDIM
                                         + (size_t)srow * HDIM + shalf * 8;
            uint32_t* hdst2 = hs + srow * WST + shalf * 4;
#pragma unroll
            for (int pp = 0; pp < 4; pp++) {
                int p = (wid << 2) + pp;
                uint4 v = __ldcg((const uint4*)(hbase + p * 16));
                *(uint4*)(hdst2 + p * 8) = v;
            }
        }
        __syncthreads();

        // ---- dots: 16 k-tiles x 2 n-tiles x 2 variants (h*Whi + h*Wlo) ----
        float D[4][4];
#pragma unroll
        for (int i = 0; i < 4; i++)
            D[i][0] = D[i][1] = D[i][2] = D[i][3] = 0.f;

#pragma unroll 4
        for (int j = 0; j < 16; j++) {
            int w = kw0 + j * 8;
            uint32_t ah0 = hs[hb0 + w],     ah1 = hs[hb1 + w];
            uint32_t ah2 = hs[hb0 + w + 4], ah3 = hs[hb1 + w + 4];
            uint32_t bh00 = ws_hi[wb0 + w], bh01 = ws_hi[wb0 + w + 4];
            uint32_t bl00 = ws_lo[wb0 + w], bl01 = ws_lo[wb0 + w + 4];
            uint32_t bh10 = ws_hi[wb1 + w], bh11 = ws_hi[wb1 + w + 4];
            uint32_t bl10 = ws_lo[wb1 + w], bl11 = ws_lo[wb1 + w + 4];
            mma16816(D[0][0], D[0][1], D[0][2], D[0][3], ah0, ah1, ah2, ah3, bh00, bh01);
            mma16816(D[1][0], D[1][1], D[1][2], D[1][3], ah0, ah1, ah2, ah3, bl00, bl01);
            mma16816(D[2][0], D[2][1], D[2][2], D[2][3], ah0, ah1, ah2, ah3, bh10, bh11);
            mma16816(D[3][0], D[3][1], D[3][2], D[3][3], ah0, ah1, ah2, ah3, bl10, bl11);
        }

        // ---- epilogue: combine variants, store to this k-half's gs plane ----
        {
            float s0, s1, s2, s3;
            s0 = D[0][0] + D[1][0];
            s1 = D[0][1] + D[1][1];
            s2 = D[0][2] + D[1][2];
            s3 = D[0][3] + D[1][3];
            gso[g * GSP + nc0 + tig * 2 + 0] = s0;
            gso[g * GSP + nc0 + tig * 2 + 1] = s1;
            gso[(g + 8) * GSP + nc0 + tig * 2 + 0] = s2;
            gso[(g + 8) * GSP + nc0 + tig * 2 + 1] = s3;
            s0 = D[2][0] + D[3][0];
            s1 = D[2][1] + D[3][1];
            s2 = D[2][2] + D[3][2];
            s3 = D[2][3] + D[3][3];
            gso[g * GSP + nc0 + 8 + tig * 2 + 0] = s0;
            gso[g * GSP + nc0 + 8 + tig * 2 + 1] = s1;
            gso[(g + 8) * GSP + nc0 + 8 + tig * 2 + 0] = s2;
            gso[(g + 8) * GSP + nc0 + 8 + tig * 2 + 1] = s3;
        }
        __syncthreads();

        // ---- update: sum k-halves + xp, activate, bf16 h store ----
        {
            const float* g0 = gs2 + ub * GSP;
            const float* g1 = gs2 + 16 * GSP + ub * GSP;
            float gi = g0[ 0 + uj] + g1[ 0 + uj] + xvi;
            float gf = g0[16 + uj] + g1[16 + uj] + xvf;
            float gg = g0[32 + uj] + g1[32 + uj] + xvg;
            float go = g0[48 + uj] + g1[48 + uj] + xvo;
            float i_ = sigf(gi), f_ = sigf(gf);
            float gv = tanhf_fast(gg), o_ = sigf(go);
            cstate = fmaf(f_, cstate, i_ * gv);
            float h = o_ * tanhf_fast(cstate);
            if (t & 1) *hh0 = __float2bfloat16(h);
            else       *hh1 = __float2bfloat16(h);
            if (t == SEQ - 1)
                g_last[batch * (2 * HDIM) + jcol] = h;
            else {
                const size_t off = tstride * (size_t)(t + 1);
                xvi = __ldcs(xpi + off); xvf = __ldcs(xpf + off);
                xvg = __ldcs(xpg + off); xvo = __ldcs(xpo + off);
            }
        }

        if (t < SEQ - 1)
            WARP_RELEASE(t + 1);
    }
}

// ================================================================
// Kernel 3b: reset all 1024 (block,warp) flags after the scan.
// ================================================================
__global__ void reset_flags_kernel()
{
    g_flags[threadIdx.x][0] = 0ull;
}

// ================================================================
// Kernel 4: final FC (unchanged).
// ================================================================
__global__ void __launch_bounds__(512) fc_kernel(
    const float* __restrict__ Wfc, const float* __restrict__ bfc,
    float* __restrict__ out)
{
    __shared__ float ls[2 * HDIM];
    const int b = blockIdx.x, tid = threadIdx.x;
    if (tid < 256)
        ((float4*)ls)[tid] = ((const float4*)(g_last + (size_t)b * 2 * HDIM))[tid];
    __syncthreads();

    const int o = tid >> 2, q = tid & 3;
    const float4* wp = (const float4*)(Wfc + (size_t)o * (2 * HDIM)) + q * 64;
    const float4* lv = (const float4*)ls + q * 64;
    float acc = 0.f;
#pragma unroll 16
    for (int k = 0; k < 64; k++) {
        float4 w = __ldg(wp + k);
        float4 l = lv[k];
        acc += w.x * l.x + w.y * l.y + w.z * l.z + w.w * l.w;
    }
    acc += __shfl_xor_sync(0xffffffff, acc, 1);
    acc += __shfl_xor_sync(0xffffffff, acc, 2);
    if (q == 0) out[b * ODIM + o] = acc + bfc[o];
}

// ================================================================
extern "C" void kernel_launch(void* const* d_in, const int* in_sizes, int n_in,
                              void* d_out, int out_size)
{
    const float* x      = (const float*)d_in[0];
    const float* W_ih_f = (const float*)d_in[1];
    const float* W_hh_f = (const float*)d_in[2];
    const float* b_f    = (const float*)d_in[3];
    const float* W_ih_b = (const float*)d_in[4];
    const float* b_b    = (const float*)d_in[6];
    const float* W_fc   = (const float*)d_in[7];
    const float* b_fc   = (const float*)d_in[8];
    float* out = (float*)d_out;

    cudaFuncSetAttribute(gemm_xp_kernel,
                         cudaFuncAttributeMaxDynamicSharedMemorySize, XGEMM_SMEM);
    cudaFuncSetAttribute(lstm_scan_kernel,
                         cudaFuncAttributeMaxDynamicSharedMemorySize, SCAN_SMEM);

    gemm_xp_kernel<<<dim3(G4 / XBN, SEQ / 2), 256, XGEMM_SMEM>>>(x, W_ih_f, b_f);
    bwd_last_kernel<<<dim3(BATCH, 2), 256>>>(x, W_ih_b, b_b);
    lstm_scan_kernel<<<SCAN_BLOCKS, SCAN_THREADS, SCAN_SMEM>>>(W_hh_f);
    reset_flags_kernel<<<1, 1024>>>();
    fc_kernel<<<BATCH, 512>>>(W_fc, b_fc, out);
}